// round 2
// baseline (speedup 1.0000x reference)
#include <cuda_runtime.h>
#include <math.h>

#define B_    8
#define C_    512
#define HW    4096            // 64*64
#define NPIX  (B_*HW)         // 32768
#define ELEMS (B_*C_*HW)      // 16777216
#define NBH   64              // B_*heads
#define NSPLIT 16

// ---------------- scratch (static device memory; no allocation at runtime) ----
__device__ float g_fm [ELEMS];
__device__ float g_q0 [ELEMS];
__device__ float g_k0 [ELEMS];
__device__ float g_v0 [ELEMS];
__device__ float g_qd [ELEMS];
__device__ float g_kd [ELEMS];
__device__ float g_vd [ELEMS];
__device__ float g_att[ELEMS];
__device__ float g_ctxp[NSPLIT * NBH * 64 * 64];   // split-K partials, reduced deterministically
__device__ float g_kmax[B_ * C_];
__device__ float g_krcp[B_ * C_];

// ---------------- 1) channel layernorm --------------------------------------
__global__ void __launch_bounds__(256) ln_k(const float* __restrict__ x,
                                            const float* __restrict__ g)
{
    int p  = blockIdx.x * 256 + threadIdx.x;     // global pixel (b*4096+hw)
    if (p >= NPIX) return;
    int b  = p >> 12;
    int hw = p & 4095;
    const float* xp = x + (size_t)b * C_ * HW + hw;
    float s = 0.f, ss = 0.f;
    for (int c = 0; c < C_; c++) {
        float v = xp[(size_t)c * HW];
        s += v; ss += v * v;
    }
    float mean = s * (1.f / C_);
    float var  = ss * (1.f / C_) - mean * mean;
    float inv  = rsqrtf(var + 1e-5f);
    float* op  = g_fm + (size_t)b * C_ * HW + hw;
    for (int c = 0; c < C_; c++)
        op[(size_t)c * HW] = (xp[(size_t)c * HW] - mean) * inv * g[c];
}

// ---------------- 2) SGEMM: C[o][n] = sum_c A[o][c] * B[c][n], per batch z ---
// M=512, N=4096, K=512.  128x128 tile, BK=16, 8x8 microtile, 256 threads.
__global__ void __launch_bounds__(256) sgemm_k(const float* __restrict__ A,
                                               const float* __restrict__ Bg,
                                               float* __restrict__ Cg)
{
    __shared__ float As[16][128];
    __shared__ float Bs[16][128];
    const int K = C_, N = HW;
    const float* Bp = Bg + (size_t)blockIdx.z * C_ * HW;
    float*       Cp = Cg + (size_t)blockIdx.z * C_ * HW;
    int tid  = threadIdx.x;
    int brow = blockIdx.y * 128;
    int bcol = blockIdx.x * 128;

    int aRow = tid >> 1;
    int aCol = (tid & 1) * 8;
    int bRow = tid >> 4;
    int bCol = (tid & 15) * 8;
    int tx = tid & 15, ty = tid >> 4;

    float acc[8][8];
    #pragma unroll
    for (int i = 0; i < 8; i++)
        #pragma unroll
        for (int j = 0; j < 8; j++) acc[i][j] = 0.f;

    const float* Aptr = A  + (brow + aRow) * K + aCol;
    const float* Bptr = Bp + bRow * N + bcol + bCol;

    for (int k0 = 0; k0 < K; k0 += 16) {
        float4 a0 = *(const float4*)(Aptr + k0);
        float4 a1 = *(const float4*)(Aptr + k0 + 4);
        float4 b0 = *(const float4*)(Bptr + k0 * N);
        float4 b1 = *(const float4*)(Bptr + k0 * N + 4);
        As[aCol+0][aRow] = a0.x; As[aCol+1][aRow] = a0.y;
        As[aCol+2][aRow] = a0.z; As[aCol+3][aRow] = a0.w;
        As[aCol+4][aRow] = a1.x; As[aCol+5][aRow] = a1.y;
        As[aCol+6][aRow] = a1.z; As[aCol+7][aRow] = a1.w;
        *(float4*)&Bs[bRow][bCol]     = b0;
        *(float4*)&Bs[bRow][bCol + 4] = b1;
        __syncthreads();
        #pragma unroll
        for (int kk = 0; kk < 16; kk++) {
            float ar[8], br[8];
            *(float4*)&ar[0] = *(const float4*)&As[kk][ty * 8];
            *(float4*)&ar[4] = *(const float4*)&As[kk][ty * 8 + 4];
            *(float4*)&br[0] = *(const float4*)&Bs[kk][tx * 8];
            *(float4*)&br[4] = *(const float4*)&Bs[kk][tx * 8 + 4];
            #pragma unroll
            for (int i = 0; i < 8; i++)
                #pragma unroll
                for (int j = 0; j < 8; j++)
                    acc[i][j] += ar[i] * br[j];
        }
        __syncthreads();
    }
    #pragma unroll
    for (int i = 0; i < 8; i++) {
        float* crow = Cp + (brow + ty * 8 + i) * N + bcol + tx * 8;
        *(float4*)crow       = make_float4(acc[i][0], acc[i][1], acc[i][2], acc[i][3]);
        *(float4*)(crow + 4) = make_float4(acc[i][4], acc[i][5], acc[i][6], acc[i][7]);
    }
}

// ---------------- 3) depthwise 3x3, pad 1 ------------------------------------
__global__ void __launch_bounds__(256) dwconv_k(const float* __restrict__ in,
                                                const float* __restrict__ w,
                                                float* __restrict__ out)
{
    int idx = blockIdx.x * 256 + threadIdx.x;
    if (idx >= ELEMS) return;
    int xx = idx & 63;
    int yy = (idx >> 6) & 63;
    int c  = (idx >> 12) & 511;
    const float* ip = in + (idx & ~4095);
    const float* wp = w + c * 9;
    float acc = 0.f;
    #pragma unroll
    for (int dy = 0; dy < 3; dy++) {
        int sy = yy + dy - 1;
        if (sy < 0 || sy > 63) continue;
        #pragma unroll
        for (int dx = 0; dx < 3; dx++) {
            int sx = xx + dx - 1;
            if (sx < 0 || sx > 63) continue;
            acc += ip[sy * 64 + sx] * wp[dy * 3 + dx];
        }
    }
    out[idx] = acc;
}

// ---------------- 4) k softmax stats (over token dim, per (b,c) row) --------
__global__ void __launch_bounds__(256) kstats_k(const float* __restrict__ kin)
{
    int row = blockIdx.x;                         // 0..B_*C_-1
    const float* p = kin + (size_t)row * HW;
    int tid = threadIdx.x;
    __shared__ float red[256];
    float m = -1e30f;
    for (int i = tid; i < HW; i += 256) m = fmaxf(m, p[i]);
    red[tid] = m; __syncthreads();
    for (int s = 128; s > 0; s >>= 1) {
        if (tid < s) red[tid] = fmaxf(red[tid], red[tid + s]);
        __syncthreads();
    }
    m = red[0];
    __syncthreads();
    float s = 0.f;
    for (int i = tid; i < HW; i += 256) s += expf(p[i] - m);
    red[tid] = s; __syncthreads();
    for (int st = 128; st > 0; st >>= 1) {
        if (tid < st) red[tid] += red[tid + st];
        __syncthreads();
    }
    if (tid == 0) { g_kmax[row] = m; g_krcp[row] = 1.f / red[0]; }
}

// ---------------- 5) ctx partials: ctx[d][e] += sum_n softk[d][n]*v[e][n] ----
__global__ void __launch_bounds__(256) ctx_k(const float* __restrict__ kin,
                                             const float* __restrict__ vin)
{
    int bh    = blockIdx.y;                       // 0..63
    int split = blockIdx.x;                       // 0..15 -> 256 tokens each
    int b = bh >> 3, h = bh & 7;
    int nbase = split * 256;
    const float* kp   = kin + (size_t)(b * C_ + h * 64) * HW;
    const float* vp   = vin + (size_t)(b * C_ + h * 64) * HW;
    const float* mrow = g_kmax + b * C_ + h * 64;
    const float* rrow = g_krcp + b * C_ + h * 64;
    __shared__ float kT[64][65];
    __shared__ float vT[64][65];
    int tid = threadIdx.x;
    int d0 = (tid >> 4) * 4;
    int e0 = (tid & 15) * 4;
    float acc[4][4];
    #pragma unroll
    for (int i = 0; i < 4; i++)
        #pragma unroll
        for (int j = 0; j < 4; j++) acc[i][j] = 0.f;

    for (int chunk = 0; chunk < 4; chunk++) {
        int n0 = nbase + chunk * 64;
        for (int i = tid; i < 64 * 64; i += 256) {
            int d = i >> 6, nn = i & 63;
            float kv = kp[d * HW + n0 + nn];
            kT[d][nn] = expf(kv - mrow[d]) * rrow[d];
            vT[d][nn] = vp[d * HW + n0 + nn];
        }
        __syncthreads();
        #pragma unroll 8
        for (int nn = 0; nn < 64; nn++) {
            float kr[4], vr[4];
            #pragma unroll
            for (int i = 0; i < 4; i++) { kr[i] = kT[d0 + i][nn]; vr[i] = vT[e0 + i][nn]; }
            #pragma unroll
            for (int i = 0; i < 4; i++)
                #pragma unroll
                for (int j = 0; j < 4; j++)
                    acc[i][j] += kr[i] * vr[j];
        }
        __syncthreads();
    }
    float* cp = g_ctxp + ((size_t)split * NBH + bh) * 4096;
    #pragma unroll
    for (int i = 0; i < 4; i++)
        #pragma unroll
        for (int j = 0; j < 4; j++)
            cp[(d0 + i) * 64 + (e0 + j)] = acc[i][j];
}

// ---------------- 6) q softmax * scale, out = q@ctx, silu --------------------
__global__ void __launch_bounds__(256) attout_k(const float* __restrict__ qin,
                                                float* __restrict__ att)
{
    int bh = blockIdx.y;
    int b = bh >> 3, h = bh & 7;
    int n = blockIdx.x * 256 + threadIdx.x;
    __shared__ float ctx_s[64][64];
    // deterministic reduce of split-K partials (L2-resident)
    for (int i = threadIdx.x; i < 4096; i += 256) {
        float s = 0.f;
        #pragma unroll
        for (int sp = 0; sp < NSPLIT; sp++)
            s += g_ctxp[((size_t)sp * NBH + bh) * 4096 + i];
        ctx_s[i >> 6][i & 63] = s;
    }
    __syncthreads();

    const float* qp = qin + (size_t)(b * C_ + h * 64) * HW + n;
    float q[64];
    float m = -1e30f;
    #pragma unroll
    for (int d = 0; d < 64; d++) { q[d] = qp[d * HW]; m = fmaxf(m, q[d]); }
    float s = 0.f;
    #pragma unroll
    for (int d = 0; d < 64; d++) { q[d] = expf(q[d] - m); s += q[d]; }
    float r = 0.125f / s;                       // scale = d^-0.5 folded in
    #pragma unroll
    for (int d = 0; d < 64; d++) q[d] *= r;

    float* op = att + (size_t)(b * C_ + h * 64) * HW + n;
    #pragma unroll
    for (int ec = 0; ec < 4; ec++) {
        float acc[16];
        #pragma unroll
        for (int j = 0; j < 16; j++) acc[j] = 0.f;
        #pragma unroll
        for (int d = 0; d < 64; d++) {
            float qd = q[d];
            const float* crow = &ctx_s[d][ec * 16];
            #pragma unroll
            for (int j = 0; j < 16; j++) acc[j] += qd * crow[j];
        }
        #pragma unroll
        for (int j = 0; j < 16; j++) {
            float xv = acc[j];
            float sg = 1.f / (1.f + expf(-xv));
            op[(ec * 16 + j) * HW] = xv * sg;       // silu
        }
    }
}

// ---------------- host orchestration -----------------------------------------
static float* symaddr(const void* sym)
{
    void* p = nullptr;
    cudaGetSymbolAddress(&p, sym);
    return (float*)p;
}

extern "C" void kernel_launch(void* const* d_in, const int* in_sizes, int n_in,
                              void* d_out, int out_size)
{
    const float* fmap = (const float*)d_in[0];
    const float* g    = (const float*)d_in[1];
    const float* wq1  = (const float*)d_in[2];
    const float* wqdw = (const float*)d_in[3];
    const float* wk1  = (const float*)d_in[4];
    const float* wkdw = (const float*)d_in[5];
    const float* wv1  = (const float*)d_in[6];
    const float* wvdw = (const float*)d_in[7];
    const float* wout = (const float*)d_in[8];
    float* out = (float*)d_out;

    float* fm  = symaddr(g_fm);
    float* q0  = symaddr(g_q0);
    float* k0  = symaddr(g_k0);
    float* v0  = symaddr(g_v0);
    float* qd  = symaddr(g_qd);
    float* kd  = symaddr(g_kd);
    float* vd  = symaddr(g_vd);
    float* att = symaddr(g_att);

    // 1) layernorm
    ln_k<<<NPIX / 256, 256>>>(fmap, g);

    // 2) q/k/v pointwise convs (batched SGEMM)
    dim3 gg(HW / 128, C_ / 128, B_);        // 32 x 4 x 8
    sgemm_k<<<gg, 256>>>(wq1, fm, q0);
    sgemm_k<<<gg, 256>>>(wk1, fm, k0);
    sgemm_k<<<gg, 256>>>(wv1, fm, v0);

    // 3) depthwise 3x3
    int dwblocks = ELEMS / 256;
    dwconv_k<<<dwblocks, 256>>>(q0, wqdw, qd);
    dwconv_k<<<dwblocks, 256>>>(k0, wkdw, kd);
    dwconv_k<<<dwblocks, 256>>>(v0, wvdw, vd);

    // 4) k softmax stats (over tokens)
    kstats_k<<<B_ * C_, 256>>>(kd);

    // 5) ctx = softk^T v  (split-K partials, deterministic)
    ctx_k<<<dim3(NSPLIT, NBH), 256>>>(kd, vd);

    // 6) q softmax + out = q@ctx + silu
    attout_k<<<dim3(HW / 256, NBH), 256>>>(qd, att);

    // 7) final pointwise conv -> d_out
    sgemm_k<<<gg, 256>>>(wout, att, out);

    (void)in_sizes; (void)n_in; (void)out_size;
}

// round 3
// speedup vs baseline: 2.1543x; 2.1543x over previous
#include <cuda_runtime.h>
#include <cuda_bf16.h>
#include <math.h>
#include <stdint.h>

#define B_    8
#define C_    512
#define HW    4096            // 64*64
#define NPIX  (B_*HW)         // 32768
#define ELEMS (B_*C_*HW)      // 16777216
#define NBH   64              // B_*heads
#define NSPLIT 16

// ---------------- scratch (static device memory; no runtime allocation) ------
__device__ __nv_bfloat16 g_fm_hi[ELEMS];
__device__ __nv_bfloat16 g_fm_lo[ELEMS];
__device__ __nv_bfloat16 g_att_hi[ELEMS];
__device__ __nv_bfloat16 g_att_lo[ELEMS];
__device__ float g_q0 [ELEMS];
__device__ float g_k0 [ELEMS];
__device__ float g_v0 [ELEMS];
__device__ float g_qd [ELEMS];
__device__ float g_kd [ELEMS];
__device__ float g_vd [ELEMS];
__device__ float g_ctxp[NSPLIT * NBH * 64 * 64];
__device__ float g_kmax[B_ * C_];
__device__ float g_krcp[B_ * C_];
// transposed + split weights: [k][m] layout, bf16 hi/lo
__device__ __nv_bfloat16 g_wt_hi[4][C_ * C_];
__device__ __nv_bfloat16 g_wt_lo[4][C_ * C_];

// ---------------- PTX helpers -------------------------------------------------
__device__ __forceinline__ uint32_t smem_u32(const void* p) {
    return (uint32_t)__cvta_generic_to_shared(p);
}
__device__ __forceinline__ void cp16(uint32_t dst, const void* src) {
    asm volatile("cp.async.cg.shared.global [%0], [%1], 16;\n" :: "r"(dst), "l"(src));
}
__device__ __forceinline__ void ldsm4t(uint32_t& r0, uint32_t& r1, uint32_t& r2, uint32_t& r3,
                                       uint32_t addr) {
    asm volatile("ldmatrix.sync.aligned.m8n8.x4.trans.shared.b16 {%0,%1,%2,%3}, [%4];\n"
                 : "=r"(r0), "=r"(r1), "=r"(r2), "=r"(r3) : "r"(addr));
}
__device__ __forceinline__ void mma16816(float* c, const uint32_t* a, const uint32_t* b) {
    asm volatile("mma.sync.aligned.m16n8k16.row.col.f32.bf16.bf16.f32 "
                 "{%0,%1,%2,%3}, {%4,%5,%6,%7}, {%8,%9}, {%0,%1,%2,%3};\n"
                 : "+f"(c[0]), "+f"(c[1]), "+f"(c[2]), "+f"(c[3])
                 : "r"(a[0]), "r"(a[1]), "r"(a[2]), "r"(a[3]), "r"(b[0]), "r"(b[1]));
}
__device__ __forceinline__ void split_bf16(float v, __nv_bfloat16& h, __nv_bfloat16& l) {
    h = __float2bfloat16(v);
    l = __float2bfloat16(v - __bfloat162float(h));
}

// ---------------- 0) weight transpose + bf16 split ---------------------------
__global__ void __launch_bounds__(256) convw_k(const float* __restrict__ W,
                                               __nv_bfloat16* __restrict__ Th,
                                               __nv_bfloat16* __restrict__ Tl)
{
    __shared__ float tile[32][33];
    int mb = blockIdx.x * 32, kb = blockIdx.y * 32;
    int tx = threadIdx.x & 31, ty = threadIdx.x >> 5;   // 32 x 8
    #pragma unroll
    for (int i = 0; i < 32; i += 8)
        tile[ty + i][tx] = W[(mb + ty + i) * C_ + kb + tx];
    __syncthreads();
    #pragma unroll
    for (int i = 0; i < 32; i += 8) {
        float v = tile[tx][ty + i];                    // W[mb+tx][kb+ty+i]
        __nv_bfloat16 h, l; split_bf16(v, h, l);
        Th[(kb + ty + i) * C_ + mb + tx] = h;
        Tl[(kb + ty + i) * C_ + mb + tx] = l;
    }
}

// ---------------- 1) channel layernorm -> bf16 hi/lo -------------------------
__global__ void __launch_bounds__(256) ln_k(const float* __restrict__ x,
                                            const float* __restrict__ g)
{
    int p  = blockIdx.x * 256 + threadIdx.x;
    if (p >= NPIX) return;
    int b  = p >> 12;
    int hw = p & 4095;
    const float* xp = x + (size_t)b * C_ * HW + hw;
    float s = 0.f, ss = 0.f;
    for (int c = 0; c < C_; c++) {
        float v = xp[(size_t)c * HW];
        s += v; ss += v * v;
    }
    float mean = s * (1.f / C_);
    float var  = ss * (1.f / C_) - mean * mean;
    float inv  = rsqrtf(var + 1e-5f);
    size_t base = (size_t)b * C_ * HW + hw;
    for (int c = 0; c < C_; c++) {
        float v = (xp[(size_t)c * HW] - mean) * inv * g[c];
        __nv_bfloat16 h, l; split_bf16(v, h, l);
        g_fm_hi[base + (size_t)c * HW] = h;
        g_fm_lo[base + (size_t)c * HW] = l;
    }
}

// ---------------- 2) bf16x3 tensor-core GEMM ---------------------------------
// C[m][n] = sum_k A[k][m] * B[k][n]; A: weights (K-major), B: activations.
// CTA 128x128, BK=64, 8 warps (2x4 -> 64x32 warp tiles), cp.async double-buffer.
#define STAGE_BYTES 65536      // AsHi 16K | AsLo 16K | BsHi 16K | BsLo 16K

__global__ void __launch_bounds__(256, 1) gemm_bf16x3_k(
    const __nv_bfloat16* __restrict__ Ah, const __nv_bfloat16* __restrict__ Al,
    const __nv_bfloat16* __restrict__ Bh, const __nv_bfloat16* __restrict__ Bl,
    float* __restrict__ Cg)
{
    extern __shared__ char sm[];
    const int N = HW;
    const int z = blockIdx.z;
    const __nv_bfloat16* Bhp = Bh + (size_t)z * C_ * HW;
    const __nv_bfloat16* Blp = Bl + (size_t)z * C_ * HW;
    float* Cp = Cg + (size_t)z * C_ * HW;
    const int m0 = blockIdx.y * 128, n0 = blockIdx.x * 128;
    const int tid = threadIdx.x;
    const int r0 = tid >> 4;          // copy row 0..15
    const int cc = tid & 15;          // 16B chunk 0..15

    const int wid = tid >> 5, lane = tid & 31;
    const int warpM = (wid & 1) * 64, warpN = (wid >> 1) * 32;
    const int j = lane >> 3, lr = lane & 7;

    float acc[4][4][4];
    #pragma unroll
    for (int mt = 0; mt < 4; mt++)
        #pragma unroll
        for (int nt = 0; nt < 4; nt++)
            #pragma unroll
            for (int q = 0; q < 4; q++) acc[mt][nt][q] = 0.f;

    auto tile_copy = [&](int stage, int k0) {
        char* base = sm + stage * STAGE_BYTES;
        #pragma unroll
        for (int i = 0; i < 4; i++) {
            int r = r0 + i * 16;
            uint32_t dsto = r * 256 + ((cc ^ (r & 7)) << 4);
            cp16(smem_u32(base + dsto),          Ah  + (size_t)(k0 + r) * C_ + m0 + cc * 8);
            cp16(smem_u32(base + 16384 + dsto),  Al  + (size_t)(k0 + r) * C_ + m0 + cc * 8);
            cp16(smem_u32(base + 32768 + dsto),  Bhp + (size_t)(k0 + r) * N  + n0 + cc * 8);
            cp16(smem_u32(base + 49152 + dsto),  Blp + (size_t)(k0 + r) * N  + n0 + cc * 8);
        }
        asm volatile("cp.async.commit_group;\n");
    };

    tile_copy(0, 0);
    for (int it = 0; it < 8; it++) {
        if (it < 7) {
            tile_copy((it + 1) & 1, (it + 1) * 64);
            asm volatile("cp.async.wait_group 1;\n");
        } else {
            asm volatile("cp.async.wait_group 0;\n");
        }
        __syncthreads();

        char* base = sm + (it & 1) * STAGE_BYTES;
        uint32_t aHiB = smem_u32(base);
        uint32_t aLoB = aHiB + 16384;
        uint32_t bHiB = aHiB + 32768;
        uint32_t bLoB = aHiB + 49152;

        #pragma unroll
        for (int kc = 0; kc < 4; kc++) {
            uint32_t aHi[4][4], aLo[4][4], bHi[4][2], bLo[4][2];
            int arow = kc * 16 + ((j >> 1) << 3) + lr;      // A: j&2 -> k+8
            int asw  = arow & 7;
            #pragma unroll
            for (int mt = 0; mt < 4; mt++) {
                int achunk = ((warpM + mt * 16) >> 3) + (j & 1);
                uint32_t off = arow * 256 + ((achunk ^ asw) << 4);
                ldsm4t(aHi[mt][0], aHi[mt][1], aHi[mt][2], aHi[mt][3], aHiB + off);
                ldsm4t(aLo[mt][0], aLo[mt][1], aLo[mt][2], aLo[mt][3], aLoB + off);
            }
            int brow = kc * 16 + ((j & 1) << 3) + lr;       // B: j&1 -> k+8
            int bsw  = brow & 7;
            #pragma unroll
            for (int nt2 = 0; nt2 < 2; nt2++) {
                int bchunk = ((warpN + nt2 * 16) >> 3) + (j >> 1);
                uint32_t off = brow * 256 + ((bchunk ^ bsw) << 4);
                ldsm4t(bHi[nt2 * 2][0], bHi[nt2 * 2][1],
                       bHi[nt2 * 2 + 1][0], bHi[nt2 * 2 + 1][1], bHiB + off);
                ldsm4t(bLo[nt2 * 2][0], bLo[nt2 * 2][1],
                       bLo[nt2 * 2 + 1][0], bLo[nt2 * 2 + 1][1], bLoB + off);
            }
            #pragma unroll
            for (int mt = 0; mt < 4; mt++)
                #pragma unroll
                for (int nt = 0; nt < 4; nt++) {
                    mma16816(acc[mt][nt], aHi[mt], bHi[nt]);
                    mma16816(acc[mt][nt], aLo[mt], bHi[nt]);
                    mma16816(acc[mt][nt], aHi[mt], bLo[nt]);
                }
        }
        __syncthreads();
    }

    // epilogue
    int ml = lane >> 2, nl = (lane & 3) * 2;
    #pragma unroll
    for (int mt = 0; mt < 4; mt++) {
        int m = m0 + warpM + mt * 16 + ml;
        #pragma unroll
        for (int nt = 0; nt < 4; nt++) {
            int n = n0 + warpN + nt * 8 + nl;
            *(float2*)&Cp[(size_t)m * N + n]       = make_float2(acc[mt][nt][0], acc[mt][nt][1]);
            *(float2*)&Cp[(size_t)(m + 8) * N + n] = make_float2(acc[mt][nt][2], acc[mt][nt][3]);
        }
    }
}

// ---------------- 3) depthwise 3x3, pad 1 ------------------------------------
__global__ void __launch_bounds__(256) dwconv_k(const float* __restrict__ in,
                                                const float* __restrict__ w,
                                                float* __restrict__ out)
{
    int idx = blockIdx.x * 256 + threadIdx.x;
    if (idx >= ELEMS) return;
    int xx = idx & 63;
    int yy = (idx >> 6) & 63;
    int c  = (idx >> 12) & 511;
    const float* ip = in + (idx & ~4095);
    const float* wp = w + c * 9;
    float acc = 0.f;
    #pragma unroll
    for (int dy = 0; dy < 3; dy++) {
        int sy = yy + dy - 1;
        if (sy < 0 || sy > 63) continue;
        #pragma unroll
        for (int dx = 0; dx < 3; dx++) {
            int sx = xx + dx - 1;
            if (sx < 0 || sx > 63) continue;
            acc += ip[sy * 64 + sx] * wp[dy * 3 + dx];
        }
    }
    out[idx] = acc;
}

// ---------------- 4) k softmax stats -----------------------------------------
__global__ void __launch_bounds__(256) kstats_k(const float* __restrict__ kin)
{
    int row = blockIdx.x;
    const float* p = kin + (size_t)row * HW;
    int tid = threadIdx.x;
    __shared__ float red[256];
    float m = -1e30f;
    for (int i = tid; i < HW; i += 256) m = fmaxf(m, p[i]);
    red[tid] = m; __syncthreads();
    for (int s = 128; s > 0; s >>= 1) {
        if (tid < s) red[tid] = fmaxf(red[tid], red[tid + s]);
        __syncthreads();
    }
    m = red[0];
    __syncthreads();
    float s = 0.f;
    for (int i = tid; i < HW; i += 256) s += expf(p[i] - m);
    red[tid] = s; __syncthreads();
    for (int st = 128; st > 0; st >>= 1) {
        if (tid < st) red[tid] += red[tid + st];
        __syncthreads();
    }
    if (tid == 0) { g_kmax[row] = m; g_krcp[row] = 1.f / red[0]; }
}

// ---------------- 5) ctx split-K partials ------------------------------------
__global__ void __launch_bounds__(256) ctx_k(const float* __restrict__ kin,
                                             const float* __restrict__ vin)
{
    int bh    = blockIdx.y;
    int split = blockIdx.x;
    int b = bh >> 3, h = bh & 7;
    int nbase = split * 256;
    const float* kp   = kin + (size_t)(b * C_ + h * 64) * HW;
    const float* vp   = vin + (size_t)(b * C_ + h * 64) * HW;
    const float* mrow = g_kmax + b * C_ + h * 64;
    const float* rrow = g_krcp + b * C_ + h * 64;
    __shared__ float kT[64][65];
    __shared__ float vT[64][65];
    int tid = threadIdx.x;
    int d0 = (tid >> 4) * 4;
    int e0 = (tid & 15) * 4;
    float acc[4][4];
    #pragma unroll
    for (int i = 0; i < 4; i++)
        #pragma unroll
        for (int jx = 0; jx < 4; jx++) acc[i][jx] = 0.f;

    for (int chunk = 0; chunk < 4; chunk++) {
        int n0 = nbase + chunk * 64;
        for (int i = tid; i < 64 * 64; i += 256) {
            int d = i >> 6, nn = i & 63;
            float kv = kp[d * HW + n0 + nn];
            kT[d][nn] = expf(kv - mrow[d]) * rrow[d];
            vT[d][nn] = vp[d * HW + n0 + nn];
        }
        __syncthreads();
        #pragma unroll 8
        for (int nn = 0; nn < 64; nn++) {
            float kr[4], vr[4];
            #pragma unroll
            for (int i = 0; i < 4; i++) { kr[i] = kT[d0 + i][nn]; vr[i] = vT[e0 + i][nn]; }
            #pragma unroll
            for (int i = 0; i < 4; i++)
                #pragma unroll
                for (int jx = 0; jx < 4; jx++)
                    acc[i][jx] += kr[i] * vr[jx];
        }
        __syncthreads();
    }
    float* cp = g_ctxp + ((size_t)split * NBH + bh) * 4096;
    #pragma unroll
    for (int i = 0; i < 4; i++)
        #pragma unroll
        for (int jx = 0; jx < 4; jx++)
            cp[(d0 + i) * 64 + (e0 + jx)] = acc[i][jx];
}

// ---------------- 6) q softmax + q@ctx + silu -> bf16 hi/lo ------------------
__global__ void __launch_bounds__(256) attout_k(const float* __restrict__ qin)
{
    int bh = blockIdx.y;
    int b = bh >> 3, h = bh & 7;
    int n = blockIdx.x * 256 + threadIdx.x;
    __shared__ float ctx_s[64][64];
    for (int i = threadIdx.x; i < 4096; i += 256) {
        float s = 0.f;
        #pragma unroll
        for (int sp = 0; sp < NSPLIT; sp++)
            s += g_ctxp[((size_t)sp * NBH + bh) * 4096 + i];
        ctx_s[i >> 6][i & 63] = s;
    }
    __syncthreads();

    const float* qp = qin + (size_t)(b * C_ + h * 64) * HW + n;
    float q[64];
    float m = -1e30f;
    #pragma unroll
    for (int d = 0; d < 64; d++) { q[d] = qp[d * HW]; m = fmaxf(m, q[d]); }
    float s = 0.f;
    #pragma unroll
    for (int d = 0; d < 64; d++) { q[d] = expf(q[d] - m); s += q[d]; }
    float r = 0.125f / s;
    #pragma unroll
    for (int d = 0; d < 64; d++) q[d] *= r;

    size_t obase = (size_t)(b * C_ + h * 64) * HW + n;
    #pragma unroll
    for (int ec = 0; ec < 4; ec++) {
        float acc[16];
        #pragma unroll
        for (int jx = 0; jx < 16; jx++) acc[jx] = 0.f;
        #pragma unroll
        for (int d = 0; d < 64; d++) {
            float qd = q[d];
            const float* crow = &ctx_s[d][ec * 16];
            #pragma unroll
            for (int jx = 0; jx < 16; jx++) acc[jx] += qd * crow[jx];
        }
        #pragma unroll
        for (int jx = 0; jx < 16; jx++) {
            float xv = acc[jx];
            float sg = 1.f / (1.f + expf(-xv));
            float ov = xv * sg;
            __nv_bfloat16 hh, ll; split_bf16(ov, hh, ll);
            g_att_hi[obase + (size_t)(ec * 16 + jx) * HW] = hh;
            g_att_lo[obase + (size_t)(ec * 16 + jx) * HW] = ll;
        }
    }
}

// ---------------- host orchestration -----------------------------------------
template <typename T>
static T* symaddr(const void* sym)
{
    void* p = nullptr;
    cudaGetSymbolAddress(&p, sym);
    return (T*)p;
}

extern "C" void kernel_launch(void* const* d_in, const int* in_sizes, int n_in,
                              void* d_out, int out_size)
{
    const float* fmap = (const float*)d_in[0];
    const float* g    = (const float*)d_in[1];
    const float* wq1  = (const float*)d_in[2];
    const float* wqdw = (const float*)d_in[3];
    const float* wk1  = (const float*)d_in[4];
    const float* wkdw = (const float*)d_in[5];
    const float* wv1  = (const float*)d_in[6];
    const float* wvdw = (const float*)d_in[7];
    const float* wout = (const float*)d_in[8];
    float* out = (float*)d_out;

    __nv_bfloat16* fmh = symaddr<__nv_bfloat16>(g_fm_hi);
    __nv_bfloat16* fml = symaddr<__nv_bfloat16>(g_fm_lo);
    __nv_bfloat16* ath = symaddr<__nv_bfloat16>(g_att_hi);
    __nv_bfloat16* atl = symaddr<__nv_bfloat16>(g_att_lo);
    __nv_bfloat16* wth = symaddr<__nv_bfloat16>(g_wt_hi);
    __nv_bfloat16* wtl = symaddr<__nv_bfloat16>(g_wt_lo);
    float* q0  = symaddr<float>(g_q0);
    float* k0  = symaddr<float>(g_k0);
    float* v0  = symaddr<float>(g_v0);
    float* qd  = symaddr<float>(g_qd);
    float* kd  = symaddr<float>(g_kd);
    float* vd  = symaddr<float>(g_vd);

    cudaFuncSetAttribute(gemm_bf16x3_k,
                         cudaFuncAttributeMaxDynamicSharedMemorySize, 2 * STAGE_BYTES);

    // 0) weights: transpose + bf16 split (tiny)
    dim3 wg(16, 16);
    convw_k<<<wg, 256>>>(wq1,  wth + 0 * C_ * C_, wtl + 0 * C_ * C_);
    convw_k<<<wg, 256>>>(wk1,  wth + 1 * C_ * C_, wtl + 1 * C_ * C_);
    convw_k<<<wg, 256>>>(wv1,  wth + 2 * C_ * C_, wtl + 2 * C_ * C_);
    convw_k<<<wg, 256>>>(wout, wth + 3 * C_ * C_, wtl + 3 * C_ * C_);

    // 1) layernorm -> bf16 hi/lo
    ln_k<<<NPIX / 256, 256>>>(fmap, g);

    // 2) q/k/v pointwise convs (tensor-core bf16x3 GEMM)
    dim3 gg(HW / 128, C_ / 128, B_);
    gemm_bf16x3_k<<<gg, 256, 2 * STAGE_BYTES>>>(wth + 0 * C_ * C_, wtl + 0 * C_ * C_, fmh, fml, q0);
    gemm_bf16x3_k<<<gg, 256, 2 * STAGE_BYTES>>>(wth + 1 * C_ * C_, wtl + 1 * C_ * C_, fmh, fml, k0);
    gemm_bf16x3_k<<<gg, 256, 2 * STAGE_BYTES>>>(wth + 2 * C_ * C_, wtl + 2 * C_ * C_, fmh, fml, v0);

    // 3) depthwise 3x3
    int dwblocks = ELEMS / 256;
    dwconv_k<<<dwblocks, 256>>>(q0, wqdw, qd);
    dwconv_k<<<dwblocks, 256>>>(k0, wkdw, kd);
    dwconv_k<<<dwblocks, 256>>>(v0, wvdw, vd);

    // 4) k softmax stats
    kstats_k<<<B_ * C_, 256>>>(kd);

    // 5) ctx = softk^T v (deterministic split-K)
    ctx_k<<<dim3(NSPLIT, NBH), 256>>>(kd, vd);

    // 6) q softmax + q@ctx + silu -> bf16 hi/lo
    attout_k<<<dim3(HW / 256, NBH), 256>>>(qd);

    // 7) final pointwise conv -> d_out
    gemm_bf16x3_k<<<gg, 256, 2 * STAGE_BYTES>>>(wth + 3 * C_ * C_, wtl + 3 * C_ * C_, ath, atl, out);

    (void)in_sizes; (void)n_in; (void)out_size;
}

// round 5
// speedup vs baseline: 2.5250x; 1.1720x over previous
#include <cuda_runtime.h>
#include <cuda_bf16.h>
#include <math.h>
#include <stdint.h>

#define B_    8
#define C_    512
#define HW    4096            // 64*64
#define NPIX  (B_*HW)         // 32768
#define ELEMS (B_*C_*HW)      // 16777216
#define NBH   64              // B_*heads
#define NSPLIT 16

// ---------------- scratch (static device memory; no runtime allocation) ------
__device__ __nv_bfloat16 g_fm_hi[ELEMS];
__device__ __nv_bfloat16 g_fm_lo[ELEMS];
__device__ __nv_bfloat16 g_att_hi[ELEMS];
__device__ __nv_bfloat16 g_att_lo[ELEMS];
__device__ float g_q0 [ELEMS];
__device__ float g_k0 [ELEMS];
__device__ float g_v0 [ELEMS];
__device__ float g_qd [ELEMS];
__device__ float g_kd [ELEMS];
__device__ float g_vd [ELEMS];
__device__ float g_ctxp[NSPLIT * NBH * 64 * 64];
__device__ float g_kmax[B_ * C_];
__device__ float g_krcp[B_ * C_];
__device__ __nv_bfloat16 g_wt_hi[4][C_ * C_];
__device__ __nv_bfloat16 g_wt_lo[4][C_ * C_];

// ---------------- PTX helpers -------------------------------------------------
__device__ __forceinline__ uint32_t smem_u32(const void* p) {
    return (uint32_t)__cvta_generic_to_shared(p);
}
__device__ __forceinline__ void cp16(uint32_t dst, const void* src) {
    asm volatile("cp.async.cg.shared.global [%0], [%1], 16;\n" :: "r"(dst), "l"(src));
}
__device__ __forceinline__ void ldsm4t(uint32_t& r0, uint32_t& r1, uint32_t& r2, uint32_t& r3,
                                       uint32_t addr) {
    asm volatile("ldmatrix.sync.aligned.m8n8.x4.trans.shared.b16 {%0,%1,%2,%3}, [%4];\n"
                 : "=r"(r0), "=r"(r1), "=r"(r2), "=r"(r3) : "r"(addr));
}
__device__ __forceinline__ void mma16816(float* c, const uint32_t* a, const uint32_t* b) {
    asm volatile("mma.sync.aligned.m16n8k16.row.col.f32.bf16.bf16.f32 "
                 "{%0,%1,%2,%3}, {%4,%5,%6,%7}, {%8,%9}, {%0,%1,%2,%3};\n"
                 : "+f"(c[0]), "+f"(c[1]), "+f"(c[2]), "+f"(c[3])
                 : "r"(a[0]), "r"(a[1]), "r"(a[2]), "r"(a[3]), "r"(b[0]), "r"(b[1]));
}
__device__ __forceinline__ void split_bf16(float v, __nv_bfloat16& h, __nv_bfloat16& l) {
    h = __float2bfloat16(v);
    l = __float2bfloat16(v - __bfloat162float(h));
}

// ---------------- 0) weight transpose + bf16 split (all 4 weights, 1 launch) -
__global__ void __launch_bounds__(256) convw_k(const float* __restrict__ W0,
                                               const float* __restrict__ W1,
                                               const float* __restrict__ W2,
                                               const float* __restrict__ W3)
{
    __shared__ float tile[32][33];
    int wsel = blockIdx.z;
    const float* W = (wsel == 0) ? W0 : (wsel == 1) ? W1 : (wsel == 2) ? W2 : W3;
    __nv_bfloat16* Th = g_wt_hi[wsel];
    __nv_bfloat16* Tl = g_wt_lo[wsel];
    int mb = blockIdx.x * 32, kb = blockIdx.y * 32;
    int tx = threadIdx.x & 31, ty = threadIdx.x >> 5;   // 32 x 8
    #pragma unroll
    for (int i = 0; i < 32; i += 8)
        tile[ty + i][tx] = W[(mb + ty + i) * C_ + kb + tx];
    __syncthreads();
    #pragma unroll
    for (int i = 0; i < 32; i += 8) {
        float v = tile[tx][ty + i];                    // W[mb+tx][kb+ty+i]
        __nv_bfloat16 h, l; split_bf16(v, h, l);
        Th[(kb + ty + i) * C_ + mb + tx] = h;
        Tl[(kb + ty + i) * C_ + mb + tx] = l;
    }
}

// ---------------- 1) channel layernorm -> bf16 hi/lo -------------------------
__global__ void __launch_bounds__(256) ln_k(const float* __restrict__ x,
                                            const float* __restrict__ g)
{
    int p  = blockIdx.x * 256 + threadIdx.x;
    if (p >= NPIX) return;
    int b  = p >> 12;
    int hw = p & 4095;
    const float* xp = x + (size_t)b * C_ * HW + hw;
    float s = 0.f, ss = 0.f;
    #pragma unroll 8
    for (int c = 0; c < C_; c++) {
        float v = xp[(size_t)c * HW];
        s += v; ss += v * v;
    }
    float mean = s * (1.f / C_);
    float var  = ss * (1.f / C_) - mean * mean;
    float inv  = rsqrtf(var + 1e-5f);
    size_t base = (size_t)b * C_ * HW + hw;
    #pragma unroll 8
    for (int c = 0; c < C_; c++) {
        float v = (xp[(size_t)c * HW] - mean) * inv * g[c];
        __nv_bfloat16 h, l; split_bf16(v, h, l);
        g_fm_hi[base + (size_t)c * HW] = h;
        g_fm_lo[base + (size_t)c * HW] = l;
    }
}

// ---------------- 2) bf16x3 tensor-core GEMM, 3-stage cp.async pipeline ------
// C[m][n] = sum_k A[k][m] * B[k][n]; A: weights (K-major), B: activations.
// CTA 128x128, BK=64, 8 warps (2x4 -> 64x32 warp tiles).
#define STAGE_BYTES 65536      // AsHi 16K | AsLo 16K | BsHi 16K | BsLo 16K
#define NSTAGE 3

__global__ void __launch_bounds__(256, 1) gemm_bf16x3_k(
    const __nv_bfloat16* __restrict__ Ah, const __nv_bfloat16* __restrict__ Al,
    const __nv_bfloat16* __restrict__ Bh, const __nv_bfloat16* __restrict__ Bl,
    float* __restrict__ Cg)
{
    extern __shared__ char sm[];
    const int N = HW;
    const int z = blockIdx.z;
    const __nv_bfloat16* Bhp = Bh + (size_t)z * C_ * HW;
    const __nv_bfloat16* Blp = Bl + (size_t)z * C_ * HW;
    float* Cp = Cg + (size_t)z * C_ * HW;
    const int m0 = blockIdx.y * 128, n0 = blockIdx.x * 128;
    const int tid = threadIdx.x;
    const int r0 = tid >> 4;          // copy row 0..15
    const int cc = tid & 15;          // 16B chunk 0..15

    const int wid = tid >> 5, lane = tid & 31;
    const int warpM = (wid & 1) * 64, warpN = (wid >> 1) * 32;
    const int j = lane >> 3, lr = lane & 7;

    float acc[4][4][4];
    #pragma unroll
    for (int mt = 0; mt < 4; mt++)
        #pragma unroll
        for (int nt = 0; nt < 4; nt++)
            #pragma unroll
            for (int q = 0; q < 4; q++) acc[mt][nt][q] = 0.f;

    auto tile_copy = [&](int stage, int k0) {
        char* base = sm + stage * STAGE_BYTES;
        #pragma unroll
        for (int i = 0; i < 4; i++) {
            int r = r0 + i * 16;
            uint32_t dsto = r * 256 + ((cc ^ (r & 7)) << 4);
            cp16(smem_u32(base + dsto),          Ah  + (size_t)(k0 + r) * C_ + m0 + cc * 8);
            cp16(smem_u32(base + 16384 + dsto),  Al  + (size_t)(k0 + r) * C_ + m0 + cc * 8);
            cp16(smem_u32(base + 32768 + dsto),  Bhp + (size_t)(k0 + r) * N  + n0 + cc * 8);
            cp16(smem_u32(base + 49152 + dsto),  Blp + (size_t)(k0 + r) * N  + n0 + cc * 8);
        }
        asm volatile("cp.async.commit_group;\n");
    };

    tile_copy(0, 0);
    tile_copy(1, 64);
    int stage_w = 2;
    for (int it = 0; it < 8; it++) {
        if (it + 2 < 8) {
            tile_copy(stage_w, (it + 2) * 64);
            stage_w = (stage_w + 1 == NSTAGE) ? 0 : stage_w + 1;
        } else {
            asm volatile("cp.async.commit_group;\n");
        }
        asm volatile("cp.async.wait_group 2;\n");
        __syncthreads();

        char* base = sm + (it % NSTAGE) * STAGE_BYTES;
        uint32_t aHiB = smem_u32(base);
        uint32_t aLoB = aHiB + 16384;
        uint32_t bHiB = aHiB + 32768;
        uint32_t bLoB = aHiB + 49152;

        #pragma unroll
        for (int kc = 0; kc < 4; kc++) {
            uint32_t aHi[4][4], aLo[4][4], bHi[4][2], bLo[4][2];
            int arow = kc * 16 + ((j >> 1) << 3) + lr;
            int asw  = arow & 7;
            #pragma unroll
            for (int mt = 0; mt < 4; mt++) {
                int achunk = ((warpM + mt * 16) >> 3) + (j & 1);
                uint32_t off = arow * 256 + ((achunk ^ asw) << 4);
                ldsm4t(aHi[mt][0], aHi[mt][1], aHi[mt][2], aHi[mt][3], aHiB + off);
                ldsm4t(aLo[mt][0], aLo[mt][1], aLo[mt][2], aLo[mt][3], aLoB + off);
            }
            int brow = kc * 16 + ((j & 1) << 3) + lr;
            int bsw  = brow & 7;
            #pragma unroll
            for (int nt2 = 0; nt2 < 2; nt2++) {
                int bchunk = ((warpN + nt2 * 16) >> 3) + (j >> 1);
                uint32_t off = brow * 256 + ((bchunk ^ bsw) << 4);
                ldsm4t(bHi[nt2 * 2][0], bHi[nt2 * 2][1],
                       bHi[nt2 * 2 + 1][0], bHi[nt2 * 2 + 1][1], bHiB + off);
                ldsm4t(bLo[nt2 * 2][0], bLo[nt2 * 2][1],
                       bLo[nt2 * 2 + 1][0], bLo[nt2 * 2 + 1][1], bLoB + off);
            }
            #pragma unroll
            for (int mt = 0; mt < 4; mt++)
                #pragma unroll
                for (int nt = 0; nt < 4; nt++) {
                    mma16816(acc[mt][nt], aHi[mt], bHi[nt]);
                    mma16816(acc[mt][nt], aLo[mt], bHi[nt]);
                    mma16816(acc[mt][nt], aHi[mt], bLo[nt]);
                }
        }
        __syncthreads();
    }

    int ml = lane >> 2, nl = (lane & 3) * 2;
    #pragma unroll
    for (int mt = 0; mt < 4; mt++) {
        int m = m0 + warpM + mt * 16 + ml;
        #pragma unroll
        for (int nt = 0; nt < 4; nt++) {
            int n = n0 + warpN + nt * 8 + nl;
            *(float2*)&Cp[(size_t)m * N + n]       = make_float2(acc[mt][nt][0], acc[mt][nt][1]);
            *(float2*)&Cp[(size_t)(m + 8) * N + n] = make_float2(acc[mt][nt][2], acc[mt][nt][3]);
        }
    }
}

// ---------------- 3) fused depthwise 3x3 (q,k,v) + k softmax stats -----------
// One block per (tensor, plane). Plane staged in smem; k-tensor blocks also
// compute token-softmax stats (max, 1/sum) entirely in-block.
__global__ void __launch_bounds__(256) dw3_k(const float* __restrict__ wq,
                                             const float* __restrict__ wk,
                                             const float* __restrict__ wv)
{
    __shared__ float sp[HW];       // 16 KB input plane
    __shared__ float red[256];
    int plane = blockIdx.x;        // b*C_ + c
    int t     = blockIdx.y;        // 0=q, 1=k, 2=v
    const float* in; const float* w; float* out;
    if (t == 0)      { in = g_q0; w = wq; out = g_qd; }
    else if (t == 1) { in = g_k0; w = wk; out = g_kd; }
    else             { in = g_v0; w = wv; out = g_vd; }
    int c = plane & 511;
    const float* ip = in + (size_t)plane * HW;
    float* op = out + (size_t)plane * HW;
    int tid = threadIdx.x;

    #pragma unroll
    for (int i = 0; i < 16; i++) sp[tid + i * 256] = ip[tid + i * 256];
    float wr[9];
    #pragma unroll
    for (int i = 0; i < 9; i++) wr[i] = w[c * 9 + i];
    __syncthreads();

    float o[16];
    float mx = -1e30f;
    #pragma unroll
    for (int i = 0; i < 16; i++) {
        int idx = tid + i * 256;
        int xx = idx & 63, yy = idx >> 6;
        float acc = 0.f;
        #pragma unroll
        for (int dy = 0; dy < 3; dy++) {
            int sy = yy + dy - 1;
            if (sy < 0 || sy > 63) continue;
            #pragma unroll
            for (int dx = 0; dx < 3; dx++) {
                int sx = xx + dx - 1;
                if (sx < 0 || sx > 63) continue;
                acc += sp[sy * 64 + sx] * wr[dy * 3 + dx];
            }
        }
        o[i] = acc;
        op[idx] = acc;
        mx = fmaxf(mx, acc);
    }

    if (t == 1) {
        red[tid] = mx; __syncthreads();
        #pragma unroll
        for (int s = 128; s > 0; s >>= 1) {
            if (tid < s) red[tid] = fmaxf(red[tid], red[tid + s]);
            __syncthreads();
        }
        mx = red[0];
        __syncthreads();
        float s = 0.f;
        #pragma unroll
        for (int i = 0; i < 16; i++) s += expf(o[i] - mx);
        red[tid] = s; __syncthreads();
        #pragma unroll
        for (int st = 128; st > 0; st >>= 1) {
            if (tid < st) red[tid] += red[tid + st];
            __syncthreads();
        }
        if (tid == 0) { g_kmax[plane] = mx; g_krcp[plane] = 1.f / red[0]; }
    }
}

// ---------------- 5) ctx split-K partials ------------------------------------
__global__ void __launch_bounds__(256) ctx_k(const float* __restrict__ kin,
                                             const float* __restrict__ vin)
{
    int bh    = blockIdx.y;
    int split = blockIdx.x;
    int b = bh >> 3, h = bh & 7;
    int nbase = split * 256;
    const float* kp   = kin + (size_t)(b * C_ + h * 64) * HW;
    const float* vp   = vin + (size_t)(b * C_ + h * 64) * HW;
    const float* mrow = g_kmax + b * C_ + h * 64;
    const float* rrow = g_krcp + b * C_ + h * 64;
    __shared__ float kT[64][65];
    __shared__ float vT[64][65];
    int tid = threadIdx.x;
    int d0 = (tid >> 4) * 4;
    int e0 = (tid & 15) * 4;
    float acc[4][4];
    #pragma unroll
    for (int i = 0; i < 4; i++)
        #pragma unroll
        for (int jx = 0; jx < 4; jx++) acc[i][jx] = 0.f;

    for (int chunk = 0; chunk < 4; chunk++) {
        int n0 = nbase + chunk * 64;
        for (int i = tid; i < 64 * 64; i += 256) {
            int d = i >> 6, nn = i & 63;
            float kv = kp[d * HW + n0 + nn];
            kT[d][nn] = expf(kv - mrow[d]) * rrow[d];
            vT[d][nn] = vp[d * HW + n0 + nn];
        }
        __syncthreads();
        #pragma unroll 8
        for (int nn = 0; nn < 64; nn++) {
            float kr[4], vr[4];
            #pragma unroll
            for (int i = 0; i < 4; i++) { kr[i] = kT[d0 + i][nn]; vr[i] = vT[e0 + i][nn]; }
            #pragma unroll
            for (int i = 0; i < 4; i++)
                #pragma unroll
                for (int jx = 0; jx < 4; jx++)
                    acc[i][jx] += kr[i] * vr[jx];
        }
        __syncthreads();
    }
    float* cp = g_ctxp + ((size_t)split * NBH + bh) * 4096;
    #pragma unroll
    for (int i = 0; i < 4; i++)
        #pragma unroll
        for (int jx = 0; jx < 4; jx++)
            cp[(d0 + i) * 64 + (e0 + jx)] = acc[i][jx];
}

// ---------------- 6) q softmax + q@ctx + silu -> bf16 hi/lo ------------------
__global__ void __launch_bounds__(256) attout_k(const float* __restrict__ qin)
{
    int bh = blockIdx.y;
    int b = bh >> 3, h = bh & 7;
    int n = blockIdx.x * 256 + threadIdx.x;
    __shared__ float ctx_s[64][64];
    for (int i = threadIdx.x; i < 4096; i += 256) {
        float s = 0.f;
        #pragma unroll
        for (int sp = 0; sp < NSPLIT; sp++)
            s += g_ctxp[((size_t)sp * NBH + bh) * 4096 + i];
        ctx_s[i >> 6][i & 63] = s;
    }
    __syncthreads();

    const float* qp = qin + (size_t)(b * C_ + h * 64) * HW + n;
    float q[64];
    float m = -1e30f;
    #pragma unroll
    for (int d = 0; d < 64; d++) { q[d] = qp[d * HW]; m = fmaxf(m, q[d]); }
    float s = 0.f;
    #pragma unroll
    for (int d = 0; d < 64; d++) { q[d] = expf(q[d] - m); s += q[d]; }
    float r = 0.125f / s;
    #pragma unroll
    for (int d = 0; d < 64; d++) q[d] *= r;

    size_t obase = (size_t)(b * C_ + h * 64) * HW + n;
    #pragma unroll
    for (int ec = 0; ec < 4; ec++) {
        float acc[16];
        #pragma unroll
        for (int jx = 0; jx < 16; jx++) acc[jx] = 0.f;
        #pragma unroll
        for (int d = 0; d < 64; d++) {
            float qd = q[d];
            const float* crow = &ctx_s[d][ec * 16];
            #pragma unroll
            for (int jx = 0; jx < 16; jx++) acc[jx] += qd * crow[jx];
        }
        #pragma unroll
        for (int jx = 0; jx < 16; jx++) {
            float xv = acc[jx];
            float sg = 1.f / (1.f + expf(-xv));
            float ov = xv * sg;
            __nv_bfloat16 hh, ll; split_bf16(ov, hh, ll);
            g_att_hi[obase + (size_t)(ec * 16 + jx) * HW] = hh;
            g_att_lo[obase + (size_t)(ec * 16 + jx) * HW] = ll;
        }
    }
}

// ---------------- host orchestration -----------------------------------------
template <typename T>
static T* symaddr(const void* sym)
{
    void* p = nullptr;
    cudaGetSymbolAddress(&p, sym);
    return (T*)p;
}

extern "C" void kernel_launch(void* const* d_in, const int* in_sizes, int n_in,
                              void* d_out, int out_size)
{
    const float* fmap = (const float*)d_in[0];
    const float* g    = (const float*)d_in[1];
    const float* wq1  = (const float*)d_in[2];
    const float* wqdw = (const float*)d_in[3];
    const float* wk1  = (const float*)d_in[4];
    const float* wkdw = (const float*)d_in[5];
    const float* wv1  = (const float*)d_in[6];
    const float* wvdw = (const float*)d_in[7];
    const float* wout = (const float*)d_in[8];
    float* out = (float*)d_out;

    __nv_bfloat16* fmh = symaddr<__nv_bfloat16>(g_fm_hi);
    __nv_bfloat16* fml = symaddr<__nv_bfloat16>(g_fm_lo);
    __nv_bfloat16* ath = symaddr<__nv_bfloat16>(g_att_hi);
    __nv_bfloat16* atl = symaddr<__nv_bfloat16>(g_att_lo);
    __nv_bfloat16* wth = symaddr<__nv_bfloat16>(g_wt_hi);
    __nv_bfloat16* wtl = symaddr<__nv_bfloat16>(g_wt_lo);
    float* q0  = symaddr<float>(g_q0);
    float* k0  = symaddr<float>(g_k0);
    float* v0  = symaddr<float>(g_v0);
    float* qd  = symaddr<float>(g_qd);
    float* kd  = symaddr<float>(g_kd);
    float* vd  = symaddr<float>(g_vd);

    cudaFuncSetAttribute(gemm_bf16x3_k,
                         cudaFuncAttributeMaxDynamicSharedMemorySize, NSTAGE * STAGE_BYTES);

    // 0) weights: transpose + bf16 split (one launch)
    convw_k<<<dim3(16, 16, 4), 256>>>(wq1, wk1, wv1, wout);

    // 1) layernorm -> bf16 hi/lo
    ln_k<<<NPIX / 256, 256>>>(fmap, g);

    // 2) q/k/v pointwise convs (tensor-core bf16x3 GEMM, 3-stage pipeline)
    dim3 gg(HW / 128, C_ / 128, B_);
    gemm_bf16x3_k<<<gg, 256, NSTAGE * STAGE_BYTES>>>(wth + 0 * C_ * C_, wtl + 0 * C_ * C_, fmh, fml, q0);
    gemm_bf16x3_k<<<gg, 256, NSTAGE * STAGE_BYTES>>>(wth + 1 * C_ * C_, wtl + 1 * C_ * C_, fmh, fml, k0);
    gemm_bf16x3_k<<<gg, 256, NSTAGE * STAGE_BYTES>>>(wth + 2 * C_ * C_, wtl + 2 * C_ * C_, fmh, fml, v0);

    // 3) fused depthwise 3x3 (q,k,v) + k softmax stats
    dw3_k<<<dim3(B_ * C_, 3), 256>>>(wqdw, wkdw, wvdw);

    // 5) ctx = softk^T v (deterministic split-K)
    ctx_k<<<dim3(NSPLIT, NBH), 256>>>(kd, vd);

    // 6) q softmax + q@ctx + silu -> bf16 hi/lo
    attout_k<<<dim3(HW / 256, NBH), 256>>>(qd);

    // 7) final pointwise conv -> d_out
    gemm_bf16x3_k<<<gg, 256, NSTAGE * STAGE_BYTES>>>(wth + 3 * C_ * C_, wtl + 3 * C_ * C_, ath, atl, out);

    (void)q0; (void)v0;
    (void)in_sizes; (void)n_in; (void)out_size;
}